// round 1
// baseline (speedup 1.0000x reference)
#include <cuda_runtime.h>

#define HD  256      // hidden width
#define MT  32       // points per CTA
#define TPB 512      // threads per CTA

// Fused fp32 forward + 3-tangent JVP kernel.
// Streams: 0 = h (forward), 1..3 = tangents d/dx0..d/dx2.
// All four stream activations for a 32-point tile live in dynamic smem
// (4 * 32 * 256 floats = 128 KB) across both 256x256 layers.
__global__ void __launch_bounds__(TPB, 1)
divfree_kernel(const float* __restrict__ x,
               const float* __restrict__ W1, const float* __restrict__ b1,
               const float* __restrict__ W2, const float* __restrict__ b2,
               const float* __restrict__ W3, const float* __restrict__ b3,
               const float* __restrict__ Wo,
               float* __restrict__ out, int n)
{
    extern __shared__ float sb[];                    // [4][MT][HD]
    __shared__ __align__(16) float xs[MT][4];        // x tile (padded)
    __shared__ __align__(16) float woT[3][HD];       // Wo transposed
    __shared__ float Jbuf[MT][9];                    // J[k][m] per point

    const int tid  = threadIdx.x;
    const int base = blockIdx.x * MT;

    // ---- stage x tile and Wo^T into smem ----
    for (int t = tid; t < MT * 3; t += TPB) {
        int pp = base + t / 3;
        if (pp >= n) pp = n - 1;                     // clamp (padding rows)
        xs[t / 3][t % 3] = x[(size_t)pp * 3 + (t % 3)];
    }
    for (int t = tid; t < 3 * HD; t += TPB) {
        int jo = t / HD, j = t % HD;
        woT[jo][j] = Wo[(size_t)j * 3 + jo];
    }
    __syncthreads();

    // ---- layer 1: x[3] -> h1[256], tangents t_k = W1[k][:] * mask ----
    {
        const int j  = tid & (HD - 1);
        const int ph = tid >> 8;                     // 0 or 1
        const float w0 = __ldg(&W1[0 * HD + j]);
        const float w1 = __ldg(&W1[1 * HD + j]);
        const float w2 = __ldg(&W1[2 * HD + j]);
        const float bb = __ldg(&b1[j]);
        #pragma unroll
        for (int pi = 0; pi < MT / 2; ++pi) {
            const int p = ph * (MT / 2) + pi;
            float pre = fmaf(xs[p][0], w0,
                        fmaf(xs[p][1], w1,
                        fmaf(xs[p][2], w2, bb)));
            float m = pre > 0.f ? 1.f : 0.f;
            sb[(0 * MT + p) * HD + j] = fmaxf(pre, 0.f);
            sb[(1 * MT + p) * HD + j] = w0 * m;
            sb[(2 * MT + p) * HD + j] = w1 * m;
            sb[(3 * MT + p) * HD + j] = w2 * m;
        }
    }
    __syncthreads();

    // ---- thread tile mapping for dense layers ----
    const int jg = tid & 63;        // 64 column groups of 4
    const int j0 = jg << 2;
    const int pg = tid >> 6;        // 8 point groups of 4
    const int p0 = pg << 2;

    // One fused pass per layer: all 4 streams' GEMMs accumulate together;
    // h pre-activation (acc[0]) supplies the ReLU mask for the tangents.
    auto dense_layer = [&](const float* __restrict__ W,
                           const float* __restrict__ b) {
        float acc[4][4][4];
        {
            const float4 bb = __ldg(reinterpret_cast<const float4*>(b) + jg);
            #pragma unroll
            for (int pi = 0; pi < 4; ++pi) {
                acc[0][pi][0] = bb.x; acc[0][pi][1] = bb.y;
                acc[0][pi][2] = bb.z; acc[0][pi][3] = bb.w;
            }
            #pragma unroll
            for (int s = 1; s < 4; ++s)
                #pragma unroll
                for (int pi = 0; pi < 4; ++pi)
                    #pragma unroll
                    for (int jj = 0; jj < 4; ++jj) acc[s][pi][jj] = 0.f;
        }

        const float4* __restrict__ W4 = reinterpret_cast<const float4*>(W);
        // register double buffer for 4 W rows (16 floats each side)
        float wcur[4][4], wnxt[4][4];
        #pragma unroll
        for (int r = 0; r < 4; ++r) {
            float4 t = __ldg(&W4[r * (HD / 4) + jg]);
            wcur[r][0] = t.x; wcur[r][1] = t.y; wcur[r][2] = t.z; wcur[r][3] = t.w;
        }

        #pragma unroll 2
        for (int kk = 0; kk < HD; kk += 4) {
            const int kn = (kk + 4) & (HD - 1);      // wraps on last iter (harmless)
            #pragma unroll
            for (int r = 0; r < 4; ++r) {
                float4 t = __ldg(&W4[(kn + r) * (HD / 4) + jg]);
                wnxt[r][0] = t.x; wnxt[r][1] = t.y; wnxt[r][2] = t.z; wnxt[r][3] = t.w;
            }
            #pragma unroll
            for (int s = 0; s < 4; ++s) {
                #pragma unroll
                for (int pi = 0; pi < 4; ++pi) {
                    const float4 a4 = *reinterpret_cast<const float4*>(
                        &sb[((s * MT) + (p0 + pi)) * HD + kk]);   // warp broadcast
                    float av[4] = {a4.x, a4.y, a4.z, a4.w};
                    #pragma unroll
                    for (int r = 0; r < 4; ++r)
                        #pragma unroll
                        for (int jj = 0; jj < 4; ++jj)
                            acc[s][pi][jj] = fmaf(av[r], wcur[r][jj], acc[s][pi][jj]);
                }
            }
            #pragma unroll
            for (int r = 0; r < 4; ++r)
                #pragma unroll
                for (int jj = 0; jj < 4; ++jj) wcur[r][jj] = wnxt[r][jj];
        }

        __syncthreads();   // everyone done reading sb
        #pragma unroll
        for (int pi = 0; pi < 4; ++pi) {
            float msk[4];
            float4 hv;
            msk[0] = acc[0][pi][0] > 0.f ? 1.f : 0.f;
            msk[1] = acc[0][pi][1] > 0.f ? 1.f : 0.f;
            msk[2] = acc[0][pi][2] > 0.f ? 1.f : 0.f;
            msk[3] = acc[0][pi][3] > 0.f ? 1.f : 0.f;
            hv.x = fmaxf(acc[0][pi][0], 0.f);
            hv.y = fmaxf(acc[0][pi][1], 0.f);
            hv.z = fmaxf(acc[0][pi][2], 0.f);
            hv.w = fmaxf(acc[0][pi][3], 0.f);
            *reinterpret_cast<float4*>(&sb[(0 * MT + (p0 + pi)) * HD + j0]) = hv;
            #pragma unroll
            for (int s = 1; s < 4; ++s) {
                float4 tv;
                tv.x = acc[s][pi][0] * msk[0];
                tv.y = acc[s][pi][1] * msk[1];
                tv.z = acc[s][pi][2] * msk[2];
                tv.w = acc[s][pi][3] * msk[3];
                *reinterpret_cast<float4*>(&sb[(s * MT + (p0 + pi)) * HD + j0]) = tv;
            }
        }
        __syncthreads();
    };

    dense_layer(W2, b2);
    dense_layer(W3, b3);

    // ---- epilogue: J[k][m] = t3_k . Wo[:,m], then fixed combination ----
    if (tid < MT * 9) {
        const int p  = tid / 9;
        const int pr = tid - p * 9;
        const int kd = pr / 3;             // derivative direction
        const int jo = pr - kd * 3;        // coef index
        const float4* trow = reinterpret_cast<const float4*>(
            &sb[((1 + kd) * MT + p) * HD]);
        const float4* wrow = reinterpret_cast<const float4*>(&woT[jo][0]);
        float sum = 0.f;
        #pragma unroll 8
        for (int q = 0; q < HD / 4; ++q) {
            float4 a = trow[q];
            float4 w = wrow[q];
            sum = fmaf(a.x, w.x, sum);
            sum = fmaf(a.y, w.y, sum);
            sum = fmaf(a.z, w.z, sum);
            sum = fmaf(a.w, w.w, sum);
        }
        Jbuf[p][pr] = sum;
    }
    __syncthreads();
    if (tid < MT * 3) {
        const int p  = tid / 3;
        const int jo = tid - p * 3;
        if (base + p < n) {
            float v;
            if (jo == 0)      v =  Jbuf[p][3 * 1 + 0] + Jbuf[p][3 * 2 + 1];
            else if (jo == 1) v = -Jbuf[p][3 * 0 + 0] + Jbuf[p][3 * 2 + 2];
            else              v = -Jbuf[p][3 * 0 + 1] - Jbuf[p][3 * 1 + 2];
            out[(size_t)(base + p) * 3 + jo] = v;
        }
    }
}

extern "C" void kernel_launch(void* const* d_in, const int* in_sizes, int n_in,
                              void* d_out, int out_size)
{
    const float* x  = (const float*)d_in[0];
    const float* W1 = (const float*)d_in[1];
    const float* b1 = (const float*)d_in[2];
    const float* W2 = (const float*)d_in[3];
    const float* b2 = (const float*)d_in[4];
    const float* W3 = (const float*)d_in[5];
    const float* b3 = (const float*)d_in[6];
    const float* Wo = (const float*)d_in[7];
    // d_in[8] = bo: does not affect the Jacobian -> unused
    float* out = (float*)d_out;

    const int n = in_sizes[0] / 3;
    const int blocks = (n + MT - 1) / MT;
    const size_t smem = (size_t)4 * MT * HD * sizeof(float);   // 128 KB

    cudaFuncSetAttribute(divfree_kernel,
                         cudaFuncAttributeMaxDynamicSharedMemorySize,
                         (int)smem);
    divfree_kernel<<<blocks, TPB, smem>>>(x, W1, b1, W2, b2, W3, b3, Wo, out, n);
}

// round 3
// speedup vs baseline: 1.0412x; 1.0412x over previous
#include <cuda_runtime.h>
#include <cuda_bf16.h>
#include <cstdint>

#define HD   256
#define PTS  32

// Does this compilation target support tcgen05 (arch-specific sm_10xa/f)?
#if defined(__CUDA_ARCH_FEAT_SM103_ALL) || defined(__CUDA_ARCH_FEAT_SM100_ALL) || \
    defined(__CUDA_ARCH_FEAT_SM101_ALL) || defined(__CUDA_ARCH_SPECIFIC__) ||     \
    defined(__CUDA_ARCH_FAMILY_SPECIFIC__)
#define HASTC 1
#else
#define HASTC 0
#endif

// ---- pre-split, pre-swizzled bf16 W operands (blocked-atom SW128 image) ----
// layout per split: 4 K-chunks (K=64) x 32KB; within chunk: 32 N-atom-rows x 1024B
__device__ __align__(128) __nv_bfloat16 g_B2s[3][65536];
__device__ __align__(128) __nv_bfloat16 g_B3s[3][65536];

// ---------------- smem layout (byte offsets from 1KB-aligned base) ----------
#define SA0   0            // A split buffer 0 : 64KB
#define SA1   65536        // A split buffer 1 : 64KB
#define SW0   131072       // W chunk buf 0 : 32KB
#define SW1   163840       // W chunk buf 1 : 32KB
#define OBS2  196608
#define OBS3  197632
#define OWO   198656       // Wo^T [3][256]
#define OW1   201728       // W1 [3][256]
#define OB1   204800
#define OXS   205824       // x tile [32][4]
#define OMSK  206336       // 256 x 32-bit masks
#define OJ    207360       // J partials [32][3][3][2]
#define OMB   209664       // 4 mbarriers
#define OTM   209696       // tmem ptr
#define SMEM_TC (209712 + 1024)

// idesc kind::f16 bf16xbf16->fp32, M=128, N=256  (formula validated vs 0x8080490)
static constexpr uint32_t IDESC =
    (1u << 4) | (1u << 7) | (1u << 10) | ((HD / 8) << 17) | (8u << 24);
// SW128 K-major: layout=2, version=1, SBO=64 (1024B row-groups), LBO=1
static constexpr uint64_t DESC_BASE =
    (uint64_t(2) << 61) | (uint64_t(1) << 46) | (uint64_t(64) << 32) | (uint64_t(1) << 16);

__device__ __forceinline__ uint32_t smem_u32(const void* p) {
    uint32_t a;
    asm("{ .reg .u64 t; cvta.to.shared.u64 t, %1; cvt.u32.u64 %0, t; }"
        : "=r"(a) : "l"(p));
    return a;
}

// ---------------- prep: split W2/W3 into 3 bf16 levels, swizzled ------------
__global__ void prep_kernel(const float* __restrict__ W2, const float* __restrict__ W3) {
    int i = blockIdx.x * 256 + threadIdx.x;    // i = k*256 + j
    int k = i >> 8, j = i & 255;
    uint32_t off = ((uint32_t)(k >> 6) << 15) |
                   (((uint32_t)(j >> 3) << 10) | ((uint32_t)(j & 7) << 7) |
                    ((uint32_t)(k & 63) << 1));
    off ^= (off >> 3) & 0x70u;
    uint32_t di = off >> 1;

    float w = W2[i];
    __nv_bfloat16 a0 = __float2bfloat16(w);
    float r1 = w - __bfloat162float(a0);
    __nv_bfloat16 a1 = __float2bfloat16(r1);
    __nv_bfloat16 a2 = __float2bfloat16(r1 - __bfloat162float(a1));
    g_B2s[0][di] = a0; g_B2s[1][di] = a1; g_B2s[2][di] = a2;

    w = W3[i];
    a0 = __float2bfloat16(w);
    r1 = w - __bfloat162float(a0);
    a1 = __float2bfloat16(r1);
    a2 = __float2bfloat16(r1 - __bfloat162float(a1));
    g_B3s[0][di] = a0; g_B3s[1][di] = a1; g_B3s[2][di] = a2;
}

#if HASTC
// ---------------- tcgen05 helpers (compiled only on sm_103a pass) -----------
__device__ __forceinline__ void mbar_init(uint32_t m, uint32_t cnt) {
    asm volatile("mbarrier.init.shared.b64 [%0], %1;" :: "r"(m), "r"(cnt) : "memory");
}
__device__ __forceinline__ void mbar_expect(uint32_t m, uint32_t bytes) {
    asm volatile("mbarrier.arrive.expect_tx.shared.b64 _, [%0], %1;"
                 :: "r"(m), "r"(bytes) : "memory");
}
__device__ __forceinline__ void mbar_wait(uint32_t m, uint32_t parity) {
    asm volatile(
        "{\n\t.reg .pred P;\n\t"
        "WL%=:\n\t"
        "mbarrier.try_wait.parity.acquire.cta.shared::cta.b64 P, [%0], %1, 0x989680;\n\t"
        "@P bra WD%=;\n\t"
        "bra WL%=;\n\t"
        "WD%=:\n\t}"
        :: "r"(m), "r"(parity) : "memory");
}
__device__ __forceinline__ void bulk_ld(uint32_t dst, const void* src, uint32_t mbar) {
    asm volatile(
        "cp.async.bulk.shared::cluster.global.mbarrier::complete_tx::bytes "
        "[%0], [%1], %2, [%3];"
        :: "r"(dst), "l"(src), "r"(32768u), "r"(mbar) : "memory");
}
__device__ __forceinline__ void mma_bf16(uint32_t d, uint64_t ad, uint64_t bd, uint32_t en) {
    asm volatile(
        "{\n\t.reg .pred p;\n\t"
        "setp.ne.u32 p, %4, 0;\n\t"
        "tcgen05.mma.cta_group::1.kind::f16 [%0], %1, %2, %3, {%5, %5, %5, %5}, p;\n\t}"
        :: "r"(d), "l"(ad), "l"(bd), "r"(IDESC), "r"(en), "r"(0u) : "memory");
}
__device__ __forceinline__ void mma_commit(uint32_t mbar) {
    asm volatile(
        "tcgen05.commit.cta_group::1.mbarrier::arrive::one.shared::cluster.b64 [%0];"
        :: "r"(mbar) : "memory");
}
__device__ __forceinline__ void fence_async_proxy() {
    asm volatile("fence.proxy.async.shared::cta;" ::: "memory");
}
__device__ __forceinline__ void tc_fence_after() {
    asm volatile("tcgen05.fence::after_thread_sync;" ::: "memory");
}
__device__ __forceinline__ void tc_wait_ld() {
    asm volatile("tcgen05.wait::ld.sync.aligned;" ::: "memory");
}
#define LDTM_X32(r, addr) \
    asm volatile( \
        "tcgen05.ld.sync.aligned.32x32b.x32.b32 " \
        "{%0, %1, %2, %3, %4, %5, %6, %7, " \
        " %8, %9, %10, %11, %12, %13, %14, %15, " \
        " %16, %17, %18, %19, %20, %21, %22, %23, " \
        " %24, %25, %26, %27, %28, %29, %30, %31}, [%32];" \
        : "=r"((r)[0]),  "=r"((r)[1]),  "=r"((r)[2]),  "=r"((r)[3]), \
          "=r"((r)[4]),  "=r"((r)[5]),  "=r"((r)[6]),  "=r"((r)[7]), \
          "=r"((r)[8]),  "=r"((r)[9]),  "=r"((r)[10]), "=r"((r)[11]), \
          "=r"((r)[12]), "=r"((r)[13]), "=r"((r)[14]), "=r"((r)[15]), \
          "=r"((r)[16]), "=r"((r)[17]), "=r"((r)[18]), "=r"((r)[19]), \
          "=r"((r)[20]), "=r"((r)[21]), "=r"((r)[22]), "=r"((r)[23]), \
          "=r"((r)[24]), "=r"((r)[25]), "=r"((r)[26]), "=r"((r)[27]), \
          "=r"((r)[28]), "=r"((r)[29]), "=r"((r)[30]), "=r"((r)[31]) \
        : "r"(addr))

// A operand bf16 store: row r (0..127), col k (0..255), blocked-atom SW128
__device__ __forceinline__ void store_a(char* sA, int r, int k, __nv_bfloat16 v) {
    uint32_t off = ((uint32_t)(k >> 6) << 14) |
                   (((uint32_t)(r >> 3) << 10) | ((uint32_t)(r & 7) << 7) |
                    ((uint32_t)(k & 63) << 1));
    off ^= (off >> 3) & 0x70u;
    *reinterpret_cast<__nv_bfloat16*>(sA + off) = v;
}
#endif  // HASTC

// =================== tcgen05 kernel (stub on non-a targets) =================
__global__ void __launch_bounds__(256, 1)
divfree_tc_kernel(const float* __restrict__ x,
                  const float* __restrict__ W1, const float* __restrict__ b1,
                  const float* __restrict__ b2, const float* __restrict__ b3,
                  const float* __restrict__ Wo,
                  float* __restrict__ out, int n)
{
#if HASTC
    extern __shared__ char smraw[];
    const uint32_t raw32 = smem_u32(smraw);
    const uint32_t sb32  = (raw32 + 1023u) & ~1023u;
    char* sb = smraw + (sb32 - raw32);

    float*    fb2 = reinterpret_cast<float*>(sb + OBS2);
    float*    fb3 = reinterpret_cast<float*>(sb + OBS3);
    float*    fwo = reinterpret_cast<float*>(sb + OWO);
    float*    fw1 = reinterpret_cast<float*>(sb + OW1);
    float*    fb1 = reinterpret_cast<float*>(sb + OB1);
    float*    fx  = reinterpret_cast<float*>(sb + OXS);
    uint32_t* msk = reinterpret_cast<uint32_t*>(sb + OMSK);
    float*    fJ  = reinterpret_cast<float*>(sb + OJ);

    const int tid  = threadIdx.x;
    const int wid  = tid >> 5;
    const int lane = tid & 31;
    const int sp   = wid & 3;     // stream / TMEM subpartition
    const int half = wid >> 2;    // column half
    const int base = blockIdx.x * PTS;

    for (int t = tid; t < HD; t += 256) { fb2[t] = b2[t]; fb3[t] = b3[t]; fb1[t] = b1[t]; }
    for (int t = tid; t < 3 * HD; t += 256) {
        fw1[t] = W1[t];
        int m = t >> 8, c = t & 255;
        fwo[m * HD + c] = Wo[(size_t)c * 3 + m];
    }
    for (int t = tid; t < PTS * 3; t += 256) {
        int p = t / 3, d = t - 3 * p;
        int pp = base + p; if (pp >= n) pp = n - 1;
        fx[p * 4 + d] = x[(size_t)pp * 3 + d];
    }
    if (tid == 0)
        for (int q = 0; q < 4; ++q) mbar_init(sb32 + OMB + q * 8, 1u);
    if (wid == 0)
        asm volatile("tcgen05.alloc.cta_group::1.sync.aligned.shared::cta.b32 [%0], %1;"
                     :: "r"(sb32 + OTM), "r"(512u) : "memory");
    __syncthreads();

    uint32_t tmem;
    asm volatile("ld.shared.b32 %0, [%1];" : "=r"(tmem) : "r"(sb32 + OTM));
    const uint32_t D2 = tmem, D3 = tmem + 256u;

    // emit v as split(s): mode 0 -> a0@SA0, a1@SA1 ; mode 1 -> a2@SA0
    auto emit = [&](int mode, int r, int c, float v) {
        __nv_bfloat16 a0 = __float2bfloat16(v);
        float r1 = v - __bfloat162float(a0);
        if (mode == 0) {
            store_a(sb + SA0, r, c, a0);
            store_a(sb + SA1, r, c, __float2bfloat16(r1));
        } else {
            __nv_bfloat16 a1 = __float2bfloat16(r1);
            store_a(sb + SA0, r, c, __float2bfloat16(r1 - __bfloat162float(a1)));
        }
    };

    // layer-1 activations + tangent seeds
    auto buildL1 = [&](int mode) {
        const int p = lane, r = (sp << 5) + p;
        const float x0 = fx[p * 4 + 0], x1 = fx[p * 4 + 1], x2 = fx[p * 4 + 2];
        const int c0 = half << 7;
        #pragma unroll 4
        for (int cc = 0; cc < 128; ++cc) {
            const int c = c0 + cc;
            float pre = fmaf(x0, fw1[c],
                        fmaf(x1, fw1[HD + c],
                        fmaf(x2, fw1[2 * HD + c], fb1[c])));
            float v = (sp == 0) ? fmaxf(pre, 0.f)
                                : ((pre > 0.f) ? fw1[(sp - 1) * HD + c] : 0.f);
            emit(mode, r, c, v);
        }
    };

    // layer-2 activations from D2 in TMEM (mode 0 also publishes masks)
    auto buildL2 = [&](int mode) {
        const int r = (sp << 5) + lane;
        if (sp == 0) {
            #pragma unroll 1
            for (int ch = 0; ch < 4; ++ch) {
                const int c0 = (half << 7) + (ch << 5);
                uint32_t regs[32];
                LDTM_X32(regs, D2 + (uint32_t)c0);
                tc_wait_ld();
                #pragma unroll 8
                for (int j = 0; j < 32; ++j) {
                    float pre = __uint_as_float(regs[j]) + fb2[c0 + j];
                    if (mode == 0) {
                        unsigned mb = __ballot_sync(0xffffffffu, pre > 0.f);
                        if (lane == 0) msk[c0 + j] = mb;
                    }
                    emit(mode, r, c0 + j, fmaxf(pre, 0.f));
                }
            }
        }
        __syncthreads();
        if (sp != 0) {
            #pragma unroll 1
            for (int ch = 0; ch < 4; ++ch) {
                const int c0 = (half << 7) + (ch << 5);
                uint32_t regs[32];
                LDTM_X32(regs, D2 + (uint32_t)c0);
                tc_wait_ld();
                #pragma unroll 8
                for (int j = 0; j < 32; ++j) {
                    const int c = c0 + j;
                    float v = ((msk[c] >> lane) & 1u) ? __uint_as_float(regs[j]) : 0.f;
                    emit(mode, r, c, v);
                }
            }
        }
    };

    // -------- MMA orchestration (tid 0) --------
    uint32_t mbF[2] = { sb32 + OMB + 0,  sb32 + OMB + 8  };
    uint32_t mbR[2] = { sb32 + OMB + 16, sb32 + OMB + 24 };
    const uint32_t wsm[2] = { sb32 + SW0, sb32 + SW1 };
    int phF[2] = {0, 0}, phR[2] = {0, 0};
    const uint64_t adesc[2] = { DESC_BASE | (((sb32 + SA0) >> 4) & 0x3FFFu),
                                DESC_BASE | (((sb32 + SA1) >> 4) & 0x3FFFu) };
    const uint64_t bdesc[2] = { DESC_BASE | ((wsm[0] >> 4) & 0x3FFFu),
                                DESC_BASE | ((wsm[1] >> 4) & 0x3FFFu) };

    // seg: run nterm terms; term t uses A buffer Asel[t] and W split Bp[t].
    auto seg = [&](uint32_t dtm, int nterm, const __nv_bfloat16* const* Bp,
                   const int* Asel, bool first) {
        const int nch = nterm * 4;
        auto load = [&](int i, int b) {
            const __nv_bfloat16* src = Bp[i >> 2] + (size_t)(i & 3) * 16384;
            mbar_expect(mbF[b], 32768u);
            bulk_ld(wsm[b], src, mbF[b]);
        };
        load(0, 0);
        if (nch > 1) load(1, 1);
        for (int i = 0; i < nch; ++i) {
            const int b = i & 1;
            mbar_wait(mbF[b], (uint32_t)phF[b]); phF[b] ^= 1;
            const uint64_t ad = adesc[Asel[i >> 2]] + (uint64_t)((i & 3) * 1024);
            #pragma unroll
            for (int m = 0; m < 4; ++m) {
                uint32_t en = (first && i == 0 && m == 0) ? 0u : 1u;
                mma_bf16(dtm, ad + (uint64_t)(m * 2), bdesc[b] + (uint64_t)(m * 2), en);
            }
            mma_commit(mbR[b]);
            if (i + 2 < nch) {
                mbar_wait(mbR[b], (uint32_t)phR[b]); phR[b] ^= 1;
                load(i + 2, b);
            }
        }
        for (int q = (nch >= 2 ? nch - 2 : 0); q < nch; ++q) {
            const int b = q & 1;
            mbar_wait(mbR[b], (uint32_t)phR[b]); phR[b] ^= 1;
        }
    };

    // ================= layer 2 (into D2) =================
    {
        buildL1(0); fence_async_proxy(); __syncthreads();
        const __nv_bfloat16* Bp5[5] = { g_B2s[0], g_B2s[1], g_B2s[2], g_B2s[0], g_B2s[1] };
        const int A5[5] = { 0, 0, 0, 1, 1 };
        if (tid == 0) seg(D2, 5, Bp5, A5, true);
        __syncthreads();
        buildL1(1); fence_async_proxy(); __syncthreads();
        const __nv_bfloat16* Bp1[1] = { g_B2s[0] };
        const int A1s[1] = { 0 };
        if (tid == 0) seg(D2, 1, Bp1, A1s, false);
        __syncthreads();
        tc_fence_after();
    }
    // ================= layer 3 (into D3) =================
    {
        buildL2(0); fence_async_proxy(); __syncthreads();
        const __nv_bfloat16* Bp5[5] = { g_B3s[0], g_B3s[1], g_B3s[2], g_B3s[0], g_B3s[1] };
        const int A5[5] = { 0, 0, 0, 1, 1 };
        if (tid == 0) seg(D3, 5, Bp5, A5, true);
        __syncthreads();
        tc_fence_after();
        buildL2(1); fence_async_proxy(); __syncthreads();
        const __nv_bfloat16* Bp1[1] = { g_B3s[0] };
        const int A1s[1] = { 0 };
        if (tid == 0) seg(D3, 1, Bp1, A1s, false);
        __syncthreads();
        tc_fence_after();
    }

    // ================= epilogue =================
    if (sp == 0) {
        #pragma unroll 1
        for (int ch = 0; ch < 4; ++ch) {
            const int c0 = (half << 7) + (ch << 5);
            uint32_t regs[32];
            LDTM_X32(regs, D3 + (uint32_t)c0);
            tc_wait_ld();
            #pragma unroll 8
            for (int j = 0; j < 32; ++j) {
                float pre = __uint_as_float(regs[j]) + fb3[c0 + j];
                unsigned mb = __ballot_sync(0xffffffffu, pre > 0.f);
                if (lane == 0) msk[c0 + j] = mb;
            }
        }
    }
    __syncthreads();
    if (sp != 0) {
        float j0 = 0.f, j1 = 0.f, j2 = 0.f;
        #pragma unroll 1
        for (int ch = 0; ch < 4; ++ch) {
            const int c0 = (half << 7) + (ch << 5);
            uint32_t regs[32];
            LDTM_X32(regs, D3 + (uint32_t)c0);
            tc_wait_ld();
            #pragma unroll 8
            for (int j = 0; j < 32; ++j) {
                const int c = c0 + j;
                if ((msk[c] >> lane) & 1u) {
                    float d = __uint_as_float(regs[j]);
                    j0 = fmaf(d, fwo[c],          j0);
                    j1 = fmaf(d, fwo[HD + c],     j1);
                    j2 = fmaf(d, fwo[2 * HD + c], j2);
                }
            }
        }
        const int kd = sp - 1;
        fJ[(((lane * 3 + kd) * 3 + 0) << 1) + half] = j0;
        fJ[(((lane * 3 + kd) * 3 + 1) << 1) + half] = j1;
        fJ[(((lane * 3 + kd) * 3 + 2) << 1) + half] = j2;
    }
    __syncthreads();
    if (tid < PTS * 3) {
        const int p = tid / 3, jo = tid - p * 3;
        auto J = [&](int kd, int m) {
            const int ix = ((p * 3 + kd) * 3 + m) << 1;
            return fJ[ix] + fJ[ix + 1];
        };
        if (base + p < n) {
            float v;
            if (jo == 0)      v =  J(1, 0) + J(2, 1);
            else if (jo == 1) v = -J(0, 0) + J(2, 2);
            else              v = -J(0, 1) - J(1, 2);
            out[(size_t)(base + p) * 3 + jo] = v;
        }
    }
    __syncthreads();
    if (wid == 0)
        asm volatile("tcgen05.dealloc.cta_group::1.sync.aligned.b32 %0, %1;"
                     :: "r"(tmem), "r"(512u));
#endif  // HASTC
}

// =================== FFMA fallback (active only when !HASTC) ================
__global__ void __launch_bounds__(512, 1)
divfree_ffma_kernel(const float* __restrict__ x,
                    const float* __restrict__ W1, const float* __restrict__ b1,
                    const float* __restrict__ W2, const float* __restrict__ b2,
                    const float* __restrict__ W3, const float* __restrict__ b3,
                    const float* __restrict__ Wo,
                    float* __restrict__ out, int n)
{
#if !HASTC
    extern __shared__ float sbf[];
    __shared__ __align__(16) float xs[PTS][4];
    __shared__ __align__(16) float woT[3][HD];
    __shared__ float Jbuf[PTS][9];

    const int tid  = threadIdx.x;
    const int base = blockIdx.x * PTS;

    for (int t = tid; t < PTS * 3; t += 512) {
        int pp = base + t / 3;
        if (pp >= n) pp = n - 1;
        xs[t / 3][t % 3] = x[(size_t)pp * 3 + (t % 3)];
    }
    for (int t = tid; t < 3 * HD; t += 512) {
        int jo = t / HD, j = t % HD;
        woT[jo][j] = Wo[(size_t)j * 3 + jo];
    }
    __syncthreads();

    {
        const int j  = tid & (HD - 1);
        const int ph = tid >> 8;
        const float w0 = __ldg(&W1[0 * HD + j]);
        const float w1 = __ldg(&W1[1 * HD + j]);
        const float w2 = __ldg(&W1[2 * HD + j]);
        const float bb = __ldg(&b1[j]);
        #pragma unroll
        for (int pi = 0; pi < PTS / 2; ++pi) {
            const int p = ph * (PTS / 2) + pi;
            float pre = fmaf(xs[p][0], w0, fmaf(xs[p][1], w1, fmaf(xs[p][2], w2, bb)));
            float m = pre > 0.f ? 1.f : 0.f;
            sbf[(0 * PTS + p) * HD + j] = fmaxf(pre, 0.f);
            sbf[(1 * PTS + p) * HD + j] = w0 * m;
            sbf[(2 * PTS + p) * HD + j] = w1 * m;
            sbf[(3 * PTS + p) * HD + j] = w2 * m;
        }
    }
    __syncthreads();

    const int jg = tid & 63;
    const int j0 = jg << 2;
    const int pg = tid >> 6;
    const int p0 = pg << 2;

    auto dense_layer = [&](const float* __restrict__ W, const float* __restrict__ b) {
        float acc[4][4][4];
        {
            const float4 bb = __ldg(reinterpret_cast<const float4*>(b) + jg);
            #pragma unroll
            for (int pi = 0; pi < 4; ++pi) {
                acc[0][pi][0] = bb.x; acc[0][pi][1] = bb.y;
                acc[0][pi][2] = bb.z; acc[0][pi][3] = bb.w;
            }
            #pragma unroll
            for (int s = 1; s < 4; ++s)
                #pragma unroll
                for (int pi = 0; pi < 4; ++pi)
                    #pragma unroll
                    for (int jj = 0; jj < 4; ++jj) acc[s][pi][jj] = 0.f;
        }
        const float4* __restrict__ W4 = reinterpret_cast<const float4*>(W);
        float wcur[4][4], wnxt[4][4];
        #pragma unroll
        for (int r = 0; r < 4; ++r) {
            float4 t = __ldg(&W4[r * (HD / 4) + jg]);
            wcur[r][0] = t.x; wcur[r][1] = t.y; wcur[r][2] = t.z; wcur[r][3] = t.w;
        }
        #pragma unroll 2
        for (int kk = 0; kk < HD; kk += 4) {
            const int kn = (kk + 4) & (HD - 1);
            #pragma unroll
            for (int r = 0; r < 4; ++r) {
                float4 t = __ldg(&W4[(kn + r) * (HD / 4) + jg]);
                wnxt[r][0] = t.x; wnxt[r][1] = t.y; wnxt[r][2] = t.z; wnxt[r][3] = t.w;
            }
            #pragma unroll
            for (int s = 0; s < 4; ++s) {
                #pragma unroll
                for (int pi = 0; pi < 4; ++pi) {
                    const float4 a4 = *reinterpret_cast<const float4*>(
                        &sbf[((s * PTS) + (p0 + pi)) * HD + kk]);
                    float av[4] = {a4.x, a4.y, a4.z, a4.w};
                    #pragma unroll
                    for (int r = 0; r < 4; ++r)
                        #pragma unroll
                        for (int jj = 0; jj < 4; ++jj)
                            acc[s][pi][jj] = fmaf(av[r], wcur[r][jj], acc[s][pi][jj]);
                }
            }
            #pragma unroll
            for (int r = 0; r < 4; ++r)
                #pragma unroll
                for (int jj = 0; jj < 4; ++jj) wcur[r][jj] = wnxt[r][jj];
        }
        __syncthreads();
        #pragma unroll
        for (int pi = 0; pi < 4; ++pi) {
            float msk[4]; float4 hv;
            msk[0] = acc[0][pi][0] > 0.f ? 1.f : 0.f;
            msk[1] = acc[0][pi][1] > 0.f ? 1.f : 0.f;
            msk[2] = acc[0][pi][2] > 0.f ? 1.f : 0.f;
            msk[3] = acc[0][pi][3] > 0.f ? 1.f : 0.f;
            hv.x = fmaxf(acc[0][pi][0], 0.f); hv.y = fmaxf(acc[0][pi][1], 0.f);
            hv.z = fmaxf(acc[0][pi][2], 0.f); hv.w = fmaxf(acc[0][pi][3], 0.f);
            *reinterpret_cast<float4*>(&sbf[(0 * PTS + (p0 + pi)) * HD + j0]) = hv;
            #pragma unroll
            for (int s = 1; s < 4; ++s) {
                float4 tv;
                tv.x = acc[s][pi][0] * msk[0]; tv.y = acc[s][pi][1] * msk[1];
                tv.z = acc[s][pi][2] * msk[2]; tv.w = acc[s][pi][3] * msk[3];
                *reinterpret_cast<float4*>(&sbf[(s * PTS + (p0 + pi)) * HD + j0]) = tv;
            }
        }
        __syncthreads();
    };

    dense_layer(W2, b2);
    dense_layer(W3, b3);

    if (tid < PTS * 9) {
        const int p  = tid / 9;
        const int pr = tid - p * 9;
        const int kd = pr / 3;
        const int jo = pr - kd * 3;
        const float4* trow = reinterpret_cast<const float4*>(&sbf[((1 + kd) * PTS + p) * HD]);
        const float4* wrow = reinterpret_cast<const float4*>(&woT[jo][0]);
        float sum = 0.f;
        #pragma unroll 8
        for (int q = 0; q < HD / 4; ++q) {
            float4 a = trow[q]; float4 w = wrow[q];
            sum = fmaf(a.x, w.x, sum); sum = fmaf(a.y, w.y, sum);
            sum = fmaf(a.z, w.z, sum); sum = fmaf(a.w, w.w, sum);
        }
        Jbuf[p][pr] = sum;
    }
    __syncthreads();
    if (tid < PTS * 3) {
        const int p  = tid / 3;
        const int jo = tid - p * 3;
        if (base + p < n) {
            float v;
            if (jo == 0)      v =  Jbuf[p][3 * 1 + 0] + Jbuf[p][3 * 2 + 1];
            else if (jo == 1) v = -Jbuf[p][3 * 0 + 0] + Jbuf[p][3 * 2 + 2];
            else              v = -Jbuf[p][3 * 0 + 1] - Jbuf[p][3 * 1 + 2];
            out[(size_t)(base + p) * 3 + jo] = v;
        }
    }
#endif  // !HASTC
}

extern "C" void kernel_launch(void* const* d_in, const int* in_sizes, int n_in,
                              void* d_out, int out_size)
{
    const float* x  = (const float*)d_in[0];
    const float* W1 = (const float*)d_in[1];
    const float* b1 = (const float*)d_in[2];
    const float* W2 = (const float*)d_in[3];
    const float* b2 = (const float*)d_in[4];
    const float* W3 = (const float*)d_in[5];
    const float* b3 = (const float*)d_in[6];
    const float* Wo = (const float*)d_in[7];
    float* out = (float*)d_out;

    const int n = in_sizes[0] / 3;
    const int blocks = (n + PTS - 1) / PTS;

    prep_kernel<<<256, 256>>>(W2, W3);

    static bool attr_done = false;
    if (!attr_done) {
        cudaFuncSetAttribute(divfree_tc_kernel,
                             cudaFuncAttributeMaxDynamicSharedMemorySize, SMEM_TC);
        cudaFuncSetAttribute(divfree_ffma_kernel,
                             cudaFuncAttributeMaxDynamicSharedMemorySize,
                             4 * PTS * HD * (int)sizeof(float));
        attr_done = true;
    }

    // Exactly one of these two has a compiled body for the active arch;
    // the other is an empty stub. Launch both -> correct either way.
    divfree_tc_kernel<<<blocks, 256, SMEM_TC>>>(x, W1, b1, b2, b3, Wo, out, n);
    divfree_ffma_kernel<<<blocks, 512, (size_t)4 * PTS * HD * sizeof(float)>>>(
        x, W1, b1, W2, b2, W3, b3, Wo, out, n);
}

// round 4
// speedup vs baseline: 2.0582x; 1.9768x over previous
#include <cuda_runtime.h>
#include <cuda_bf16.h>
#include <cstdint>

#define HD   256
#define PTS  32
#define TPB  512

#if defined(__CUDA_ARCH_FEAT_SM103_ALL) || defined(__CUDA_ARCH_FEAT_SM100_ALL) || \
    defined(__CUDA_ARCH_FEAT_SM101_ALL) || defined(__CUDA_ARCH_SPECIFIC__) ||     \
    defined(__CUDA_ARCH_FAMILY_SPECIFIC__)
#define HASTC 1
#else
#define HASTC 0
#endif

// ---- pre-split, pre-swizzled bf16 W operands (blocked-atom SW128 image) ----
// per split: 4 K-chunks (K=64) x 32KB; within chunk: 32 N-atom-rows x 1024B
__device__ __align__(128) __nv_bfloat16 g_B2s[3][65536];
__device__ __align__(128) __nv_bfloat16 g_B3s[3][65536];

// ---------------- smem layout (byte offsets from 1KB-aligned base) ----------
#define SA0    0          // A split a0 : 64KB
#define SA1    65536      // A split a1 (later a2h|0) : 64KB
#define SW0    131072     // W chunk buf 0 : 32KB
#define SW1    163840     // W chunk buf 1 : 32KB
#define STASH  196608     // a2 h-rows: 32 rows x 516B (padded) = 16512
#define OBS2   213120
#define OBS3   214144
#define OWO    215168     // Wo^T [3][256]
#define OW1    218240     // W1 [3][256]
#define OB1    221312
#define OXS    222336     // x tile [32][4]
#define OMSK   222848     // 256 x 32-bit masks
#define OJ     223872     // J partials [32][3][3][4]  (4608B)
#define OMB    228480     // 4 mbarriers
#define OTM    228544     // tmem ptr
#define SMEM_TC (228560 + 1024)

// idesc kind::f16 bf16xbf16->fp32, M=128, N=256 (validated in R3)
static constexpr uint32_t IDESC =
    (1u << 4) | (1u << 7) | (1u << 10) | ((HD / 8) << 17) | (8u << 24);
// SW128 K-major: layout=2, version=1, SBO=64, LBO=1 (validated in R3)
static constexpr uint64_t DESC_BASE =
    (uint64_t(2) << 61) | (uint64_t(1) << 46) | (uint64_t(64) << 32) | (uint64_t(1) << 16);

__device__ __forceinline__ uint32_t smem_u32(const void* p) {
    uint32_t a;
    asm("{ .reg .u64 t; cvta.to.shared.u64 t, %1; cvt.u32.u64 %0, t; }"
        : "=r"(a) : "l"(p));
    return a;
}

// ---------------- prep: split W2/W3 into 3 bf16 levels, swizzled ------------
__global__ void prep_kernel(const float* __restrict__ W2, const float* __restrict__ W3) {
    int i = blockIdx.x * 256 + threadIdx.x;    // i = k*256 + j
    int k = i >> 8, j = i & 255;
    uint32_t off = ((uint32_t)(k >> 6) << 15) |
                   (((uint32_t)(j >> 3) << 10) | ((uint32_t)(j & 7) << 7) |
                    ((uint32_t)(k & 63) << 1));
    off ^= (off >> 3) & 0x70u;
    uint32_t di = off >> 1;

    float w = W2[i];
    __nv_bfloat16 a0 = __float2bfloat16(w);
    float r1 = w - __bfloat162float(a0);
    __nv_bfloat16 a1 = __float2bfloat16(r1);
    __nv_bfloat16 a2 = __float2bfloat16(r1 - __bfloat162float(a1));
    g_B2s[0][di] = a0; g_B2s[1][di] = a1; g_B2s[2][di] = a2;

    w = W3[i];
    a0 = __float2bfloat16(w);
    r1 = w - __bfloat162float(a0);
    a1 = __float2bfloat16(r1);
    a2 = __float2bfloat16(r1 - __bfloat162float(a1));
    g_B3s[0][di] = a0; g_B3s[1][di] = a1; g_B3s[2][di] = a2;
}

#if HASTC
__device__ __forceinline__ void mbar_init(uint32_t m, uint32_t cnt) {
    asm volatile("mbarrier.init.shared.b64 [%0], %1;" :: "r"(m), "r"(cnt) : "memory");
}
__device__ __forceinline__ void mbar_expect(uint32_t m, uint32_t bytes) {
    asm volatile("mbarrier.arrive.expect_tx.shared.b64 _, [%0], %1;"
                 :: "r"(m), "r"(bytes) : "memory");
}
__device__ __forceinline__ void mbar_wait(uint32_t m, uint32_t parity) {
    asm volatile(
        "{\n\t.reg .pred P;\n\t"
        "WL%=:\n\t"
        "mbarrier.try_wait.parity.acquire.cta.shared::cta.b64 P, [%0], %1, 0x989680;\n\t"
        "@P bra WD%=;\n\t"
        "bra WL%=;\n\t"
        "WD%=:\n\t}"
        :: "r"(m), "r"(parity) : "memory");
}
__device__ __forceinline__ void bulk_ld(uint32_t dst, const void* src, uint32_t mbar) {
    asm volatile(
        "cp.async.bulk.shared::cluster.global.mbarrier::complete_tx::bytes "
        "[%0], [%1], %2, [%3];"
        :: "r"(dst), "l"(src), "r"(32768u), "r"(mbar) : "memory");
}
__device__ __forceinline__ void mma_bf16(uint32_t d, uint64_t ad, uint64_t bd, uint32_t en) {
    asm volatile(
        "{\n\t.reg .pred p;\n\t"
        "setp.ne.u32 p, %4, 0;\n\t"
        "tcgen05.mma.cta_group::1.kind::f16 [%0], %1, %2, %3, {%5, %5, %5, %5}, p;\n\t}"
        :: "r"(d), "l"(ad), "l"(bd), "r"(IDESC), "r"(en), "r"(0u) : "memory");
}
__device__ __forceinline__ void mma_commit(uint32_t mbar) {
    asm volatile(
        "tcgen05.commit.cta_group::1.mbarrier::arrive::one.shared::cluster.b64 [%0];"
        :: "r"(mbar) : "memory");
}
__device__ __forceinline__ void fence_async_proxy() {
    asm volatile("fence.proxy.async.shared::cta;" ::: "memory");
}
__device__ __forceinline__ void tc_fence_after() {
    asm volatile("tcgen05.fence::after_thread_sync;" ::: "memory");
}
__device__ __forceinline__ void tc_wait_ld() {
    asm volatile("tcgen05.wait::ld.sync.aligned;" ::: "memory");
}
#define LDTM_X32(r, addr) \
    asm volatile( \
        "tcgen05.ld.sync.aligned.32x32b.x32.b32 " \
        "{%0, %1, %2, %3, %4, %5, %6, %7, " \
        " %8, %9, %10, %11, %12, %13, %14, %15, " \
        " %16, %17, %18, %19, %20, %21, %22, %23, " \
        " %24, %25, %26, %27, %28, %29, %30, %31}, [%32];" \
        : "=r"((r)[0]),  "=r"((r)[1]),  "=r"((r)[2]),  "=r"((r)[3]), \
          "=r"((r)[4]),  "=r"((r)[5]),  "=r"((r)[6]),  "=r"((r)[7]), \
          "=r"((r)[8]),  "=r"((r)[9]),  "=r"((r)[10]), "=r"((r)[11]), \
          "=r"((r)[12]), "=r"((r)[13]), "=r"((r)[14]), "=r"((r)[15]), \
          "=r"((r)[16]), "=r"((r)[17]), "=r"((r)[18]), "=r"((r)[19]), \
          "=r"((r)[20]), "=r"((r)[21]), "=r"((r)[22]), "=r"((r)[23]), \
          "=r"((r)[24]), "=r"((r)[25]), "=r"((r)[26]), "=r"((r)[27]), \
          "=r"((r)[28]), "=r"((r)[29]), "=r"((r)[30]), "=r"((r)[31]) \
        : "r"(addr))

// A operand packed store: row r (0..127), even col k, 2 bf16 cols in one b32
__device__ __forceinline__ void store_a_pair(char* sA, int r, int k, uint32_t packed) {
    uint32_t off = ((uint32_t)(k >> 6) << 14) | ((uint32_t)(r >> 3) << 10) |
                   ((uint32_t)(r & 7) << 7)  | ((uint32_t)(k & 63) << 1);
    off ^= (off >> 3) & 0x70u;
    *reinterpret_cast<uint32_t*>(sA + off) = packed;
}
__device__ __forceinline__ uint32_t pack_bf2(float a, float b) {
    __nv_bfloat162 v = __floats2bfloat162_rn(a, b);
    return *reinterpret_cast<uint32_t*>(&v);
}
#endif  // HASTC

__global__ void __launch_bounds__(TPB, 1)
divfree_tc_kernel(const float* __restrict__ x,
                  const float* __restrict__ W1, const float* __restrict__ b1,
                  const float* __restrict__ b2, const float* __restrict__ b3,
                  const float* __restrict__ Wo,
                  float* __restrict__ out, int n)
{
#if HASTC
    extern __shared__ char smraw[];
    const uint32_t raw32 = smem_u32(smraw);
    const uint32_t sb32  = (raw32 + 1023u) & ~1023u;
    char* sb = smraw + (sb32 - raw32);

    float*    fb2 = reinterpret_cast<float*>(sb + OBS2);
    float*    fb3 = reinterpret_cast<float*>(sb + OBS3);
    float*    fwo = reinterpret_cast<float*>(sb + OWO);
    float*    fw1 = reinterpret_cast<float*>(sb + OW1);
    float*    fb1 = reinterpret_cast<float*>(sb + OB1);
    float*    fx  = reinterpret_cast<float*>(sb + OXS);
    uint32_t* msk = reinterpret_cast<uint32_t*>(sb + OMSK);
    float*    fJ  = reinterpret_cast<float*>(sb + OJ);

    const int tid  = threadIdx.x;
    const int wid  = tid >> 5;
    const int lane = tid & 31;
    const int sp   = wid & 3;     // stream / TMEM subpartition
    const int grp  = wid >> 2;    // column quarter (64 cols)
    const int base = blockIdx.x * PTS;

    for (int t = tid; t < HD; t += TPB) { fb2[t] = b2[t]; fb3[t] = b3[t]; fb1[t] = b1[t]; }
    for (int t = tid; t < 3 * HD; t += TPB) {
        fw1[t] = W1[t];
        int m = t >> 8, c = t & 255;
        fwo[m * HD + c] = Wo[(size_t)c * 3 + m];
    }
    for (int t = tid; t < PTS * 3; t += TPB) {
        int p = t / 3, d = t - 3 * p;
        int pp = base + p; if (pp >= n) pp = n - 1;
        fx[p * 4 + d] = x[(size_t)pp * 3 + d];
    }
    if (tid == 0)
        for (int q = 0; q < 4; ++q) mbar_init(sb32 + OMB + q * 8, 1u);
    if (wid == 0)
        asm volatile("tcgen05.alloc.cta_group::1.sync.aligned.shared::cta.b32 [%0], %1;"
                     :: "r"(sb32 + OTM), "r"(512u) : "memory");
    __syncthreads();

    uint32_t tmem;
    asm volatile("ld.shared.b32 %0, [%1];" : "=r"(tmem) : "r"(sb32 + OTM));
    const uint32_t D2 = tmem, D3 = tmem + 256u;

    // split two cols, store a0->SA0, a1->SA1, a2(h-rows)->stash
    auto split_store = [&](int r, int c, float vA, float vB, bool hrow, int p) {
        float a0A = __bfloat162float(__float2bfloat16(vA));
        float a0B = __bfloat162float(__float2bfloat16(vB));
        float rA = vA - a0A, rB = vB - a0B;
        store_a_pair(sb + SA0, r, c, pack_bf2(vA, vB));
        store_a_pair(sb + SA1, r, c, pack_bf2(rA, rB));
        if (hrow) {
            float a1A = __bfloat162float(__float2bfloat16(rA));
            float a1B = __bfloat162float(__float2bfloat16(rB));
            *reinterpret_cast<uint32_t*>(sb + STASH + p * 516 + c * 2) =
                pack_bf2(rA - a1A, rB - a1B);
        }
    };

    // layer-1: x -> h1 + tangent seeds (single pass, both splits + a2 stash)
    auto buildL1 = [&]() {
        const int p = lane, r = (sp << 5) + p;
        const float x0 = fx[p * 4 + 0], x1 = fx[p * 4 + 1], x2 = fx[p * 4 + 2];
        #pragma unroll 4
        for (int m = 0; m < 32; ++m) {
            const int c = (grp << 6) + 2 * m;
            float pA = fmaf(x0, fw1[c],
                       fmaf(x1, fw1[HD + c], fmaf(x2, fw1[2 * HD + c], fb1[c])));
            float pB = fmaf(x0, fw1[c + 1],
                       fmaf(x1, fw1[HD + c + 1], fmaf(x2, fw1[2 * HD + c + 1], fb1[c + 1])));
            float vA, vB;
            if (sp == 0) { vA = fmaxf(pA, 0.f); vB = fmaxf(pB, 0.f); }
            else {
                vA = (pA > 0.f) ? fw1[(sp - 1) * HD + c] : 0.f;
                vB = (pB > 0.f) ? fw1[(sp - 1) * HD + c + 1] : 0.f;
            }
            split_store(r, c, vA, vB, sp == 0, p);
        }
    };

    // layer-2: D2 -> activations (single pass, publishes masks)
    auto buildL2 = [&]() {
        const int r = (sp << 5) + lane;
        if (sp == 0) {
            #pragma unroll 1
            for (int ch = 0; ch < 2; ++ch) {
                const int c0 = (grp << 6) + (ch << 5);
                uint32_t regs[32];
                LDTM_X32(regs, D2 + (uint32_t)c0);
                tc_wait_ld();
                #pragma unroll 4
                for (int m = 0; m < 16; ++m) {
                    const int c = c0 + 2 * m;
                    float pA = __uint_as_float(regs[2 * m])     + fb2[c];
                    float pB = __uint_as_float(regs[2 * m + 1]) + fb2[c + 1];
                    unsigned mbA = __ballot_sync(0xffffffffu, pA > 0.f);
                    unsigned mbB = __ballot_sync(0xffffffffu, pB > 0.f);
                    if (lane == 0) { msk[c] = mbA; msk[c + 1] = mbB; }
                    split_store(r, c, fmaxf(pA, 0.f), fmaxf(pB, 0.f), true, lane);
                }
            }
        }
        __syncthreads();
        if (sp != 0) {
            #pragma unroll 1
            for (int ch = 0; ch < 2; ++ch) {
                const int c0 = (grp << 6) + (ch << 5);
                uint32_t regs[32];
                LDTM_X32(regs, D2 + (uint32_t)c0);
                tc_wait_ld();
                #pragma unroll 4
                for (int m = 0; m < 16; ++m) {
                    const int c = c0 + 2 * m;
                    float vA = ((msk[c] >> lane) & 1u)     ? __uint_as_float(regs[2 * m])     : 0.f;
                    float vB = ((msk[c + 1] >> lane) & 1u) ? __uint_as_float(regs[2 * m + 1]) : 0.f;
                    split_store(r, c, vA, vB, false, lane);
                }
            }
        }
    };

    // overwrite SA1: h rows <- a2 stash, tangent rows <- 0 (for the final b0 pass)
    auto rewriteSA1 = [&]() {
        for (int idx = tid; idx < 16384; idx += TPB) {
            const int r = idx >> 7, m = idx & 127;
            uint32_t v = 0u;
            if (r < 32) v = *reinterpret_cast<uint32_t*>(sb + STASH + r * 516 + m * 4);
            store_a_pair(sb + SA1, r, 2 * m, v);
        }
    };

    // -------- MMA orchestration (tid 0) --------
    uint32_t mbF[2] = { sb32 + OMB + 0,  sb32 + OMB + 8  };
    uint32_t mbR[2] = { sb32 + OMB + 16, sb32 + OMB + 24 };
    const uint32_t wsm[2] = { sb32 + SW0, sb32 + SW1 };
    int phF[2] = {0, 0}, phR[2] = {0, 0};
    const uint64_t adesc[2] = { DESC_BASE | (((sb32 + SA0) >> 4) & 0x3FFFu),
                                DESC_BASE | (((sb32 + SA1) >> 4) & 0x3FFFu) };
    const uint64_t bdesc[2] = { DESC_BASE | ((wsm[0] >> 4) & 0x3FFFu),
                                DESC_BASE | ((wsm[1] >> 4) & 0x3FFFu) };

    auto seg = [&](uint32_t dtm, int nterm, const __nv_bfloat16* const* Bp,
                   const int* Asel, bool first) {
        const int nch = nterm * 4;
        auto load = [&](int i, int b) {
            const __nv_bfloat16* src = Bp[i >> 2] + (size_t)(i & 3) * 16384;
            mbar_expect(mbF[b], 32768u);
            bulk_ld(wsm[b], src, mbF[b]);
        };
        load(0, 0);
        if (nch > 1) load(1, 1);
        for (int i = 0; i < nch; ++i) {
            const int b = i & 1;
            mbar_wait(mbF[b], (uint32_t)phF[b]); phF[b] ^= 1;
            const uint64_t ad = adesc[Asel[i >> 2]] + (uint64_t)((i & 3) * 1024);
            #pragma unroll
            for (int m = 0; m < 4; ++m) {
                uint32_t en = (first && i == 0 && m == 0) ? 0u : 1u;
                mma_bf16(dtm, ad + (uint64_t)(m * 2), bdesc[b] + (uint64_t)(m * 2), en);
            }
            mma_commit(mbR[b]);
            if (i + 2 < nch) {
                mbar_wait(mbR[b], (uint32_t)phR[b]); phR[b] ^= 1;
                load(i + 2, b);
            }
        }
        for (int q = (nch >= 2 ? nch - 2 : 0); q < nch; ++q) {
            const int b = q & 1;
            mbar_wait(mbR[b], (uint32_t)phR[b]); phR[b] ^= 1;
        }
    };

    const int A5[5] = { 0, 0, 0, 1, 1 };
    const int A1s[1] = { 1 };

    // ================= layer 2 (into D2) =================
    buildL1(); fence_async_proxy(); __syncthreads();
    {
        const __nv_bfloat16* Bp5[5] = { g_B2s[0], g_B2s[1], g_B2s[2], g_B2s[0], g_B2s[1] };
        if (tid == 0) seg(D2, 5, Bp5, A5, true);
    }
    __syncthreads();
    rewriteSA1(); fence_async_proxy(); __syncthreads();
    {
        const __nv_bfloat16* Bp1[1] = { g_B2s[0] };
        if (tid == 0) seg(D2, 1, Bp1, A1s, false);
    }
    __syncthreads(); tc_fence_after();

    // ================= layer 3 (into D3) =================
    buildL2(); fence_async_proxy(); __syncthreads();
    {
        const __nv_bfloat16* Bp5[5] = { g_B3s[0], g_B3s[1], g_B3s[2], g_B3s[0], g_B3s[1] };
        if (tid == 0) seg(D3, 5, Bp5, A5, true);
    }
    __syncthreads();
    rewriteSA1(); fence_async_proxy(); __syncthreads();
    {
        const __nv_bfloat16* Bp1[1] = { g_B3s[0] };
        if (tid == 0) seg(D3, 1, Bp1, A1s, false);
    }
    __syncthreads(); tc_fence_after();

    // ================= epilogue =================
    if (sp == 0) {
        #pragma unroll 1
        for (int ch = 0; ch < 2; ++ch) {
            const int c0 = (grp << 6) + (ch << 5);
            uint32_t regs[32];
            LDTM_X32(regs, D3 + (uint32_t)c0);
            tc_wait_ld();
            #pragma unroll 8
            for (int j = 0; j < 32; ++j) {
                float pre = __uint_as_float(regs[j]) + fb3[c0 + j];
                unsigned mb = __ballot_sync(0xffffffffu, pre > 0.f);
                if (lane == 0) msk[c0 + j] = mb;
            }
        }
    }
    __syncthreads();
    if (sp != 0) {
        float j0 = 0.f, j1 = 0.f, j2 = 0.f;
        #pragma unroll 1
        for (int ch = 0; ch < 2; ++ch) {
            const int c0 = (grp << 6) + (ch << 5);
            uint32_t regs[32];
            LDTM_X32(regs, D3 + (uint32_t)c0);
            tc_wait_ld();
            #pragma unroll 8
            for (int j = 0; j < 32; ++j) {
                const int c = c0 + j;
                if ((msk[c] >> lane) & 1u) {
                    float d = __uint_as_float(regs[j]);
                    j0 = fmaf(d, fwo[c],          j0);
                    j1 = fmaf(d, fwo[HD + c],     j1);
                    j2 = fmaf(d, fwo[2 * HD + c], j2);
                }
            }
        }
        const int kd = sp - 1;
        fJ[((lane * 3 + kd) * 3 + 0) * 4 + grp] = j0;
        fJ[((lane * 3 + kd) * 3 + 1) * 4 + grp] = j1;
        fJ[((lane * 3 + kd) * 3 + 2) * 4 + grp] = j2;
    }
    __syncthreads();
    if (tid < PTS * 3) {
        const int p = tid / 3, jo = tid - p * 3;
        auto J = [&](int kd, int m) {
            const float* q = &fJ[((p * 3 + kd) * 3 + m) * 4];
            return q[0] + q[1] + q[2] + q[3];
        };
        if (base + p < n) {
            float v;
            if (jo == 0)      v =  J(1, 0) + J(2, 1);
            else if (jo == 1) v = -J(0, 0) + J(2, 2);
            else              v = -J(0, 1) - J(1, 2);
            out[(size_t)(base + p) * 3 + jo] = v;
        }
    }
    __syncthreads();
    if (wid == 0)
        asm volatile("tcgen05.dealloc.cta_group::1.sync.aligned.b32 %0, %1;"
                     :: "r"(tmem), "r"(512u));
#endif  // HASTC
}

extern "C" void kernel_launch(void* const* d_in, const int* in_sizes, int n_in,
                              void* d_out, int out_size)
{
    const float* x  = (const float*)d_in[0];
    const float* W1 = (const float*)d_in[1];
    const float* b1 = (const float*)d_in[2];
    const float* W2 = (const float*)d_in[3];
    const float* b2 = (const float*)d_in[4];
    const float* W3 = (const float*)d_in[5];
    const float* b3 = (const float*)d_in[6];
    const float* Wo = (const float*)d_in[7];
    float* out = (float*)d_out;

    const int n = in_sizes[0] / 3;
    const int blocks = (n + PTS - 1) / PTS;

    prep_kernel<<<256, 256>>>(W2, W3);

    cudaFuncSetAttribute(divfree_tc_kernel,
                         cudaFuncAttributeMaxDynamicSharedMemorySize, SMEM_TC);
    divfree_tc_kernel<<<blocks, TPB, SMEM_TC>>>(x, W1, b1, b2, b3, Wo, out, n);
}